// round 15
// baseline (speedup 1.0000x reference)
#include <cuda_runtime.h>
#include <cuda_bf16.h>
#include <cstdint>

// Problem constants (fixed by the reference)
#define F_IN   512
#define F_OUT  256
#define MAX_NODES 100000
#define KC      64                 // K per chunk
#define NCHUNK  (F_IN / KC)        // 8
#define TILE_M  128

// ---------------------------------------------------------------------------
// Global scratch (allocation-free per harness rules)
// ---------------------------------------------------------------------------
__device__ float g_support[(size_t)MAX_NODES * F_OUT];                 // 102.4 MB
__device__ __nv_bfloat16 g_wt_hi[NCHUNK * F_OUT * KC];                 // 256 KB, [chunk][n][kk]
__device__ __nv_bfloat16 g_wt_lo[NCHUNK * F_OUT * KC];                 // 256 KB

// ---------------------------------------------------------------------------
// Helpers (baseline PTX only: ldmatrix sm_75+, mma.sync + cp.async sm_80+)
// ---------------------------------------------------------------------------
__device__ __forceinline__ uint32_t smem_to_u32(const void* p) {
    uint32_t a;
    asm("{ .reg .u64 t; cvta.to.shared.u64 t, %1; cvt.u32.u64 %0, t; }" : "=r"(a) : "l"(p));
    return a;
}
#define STS128(r0, r1, r2, r3, addr) \
    asm volatile("st.shared.v4.b32 [%0], {%1, %2, %3, %4};" \
                 :: "r"(addr), "r"(r0), "r"(r1), "r"(r2), "r"(r3) : "memory")
#define CP_ASYNC16(smem, gmem) \
    asm volatile("cp.async.cg.shared.global [%0], [%1], 16;" \
                 :: "r"(smem), "l"(gmem) : "memory")
#define CP_COMMIT()  asm volatile("cp.async.commit_group;" ::: "memory")
#define CP_WAIT0()   asm volatile("cp.async.wait_group 0;" ::: "memory")
#define LDSM_X4(r, addr) \
    asm volatile("ldmatrix.sync.aligned.m8n8.x4.shared.b16 {%0,%1,%2,%3}, [%4];" \
                 : "=r"((r)[0]), "=r"((r)[1]), "=r"((r)[2]), "=r"((r)[3]) : "r"(addr))
#define MMA_BF16(d, a, b0, b1) \
    asm volatile("mma.sync.aligned.m16n8k16.row.col.f32.bf16.bf16.f32 " \
                 "{%0,%1,%2,%3}, {%4,%5,%6,%7}, {%8,%9}, {%0,%1,%2,%3};" \
                 : "+f"((d)[0]), "+f"((d)[1]), "+f"((d)[2]), "+f"((d)[3]) \
                 : "r"((a)[0]), "r"((a)[1]), "r"((a)[2]), "r"((a)[3]), \
                   "r"(b0), "r"(b1))

// Padded SMEM row stride: 64 bf16 + 8 pad = 72 elem = 144 B (conflict-free ldmatrix)
#define ROWB     144
#define SM_AHI   0
#define SM_ALO   (SM_AHI + TILE_M * ROWB)    // 18432
#define SM_BHI   (SM_ALO + TILE_M * ROWB)    // 36864
#define SM_BLO   (SM_BHI + 128 * ROWB)       // 55296
#define SM_STAGE (SM_BLO + 128 * ROWB)       // 73728 B per stage
#define SM_TOTAL (2 * SM_STAGE)              // 147456 B (double-buffered)

__device__ __forceinline__ void split_pack2(float a, float b, uint32_t& hi, uint32_t& lo) {
    __nv_bfloat16 ha = __float2bfloat16(a);
    __nv_bfloat16 hb = __float2bfloat16(b);
    __nv_bfloat162 hp; hp.x = ha; hp.y = hb;
    hi = *reinterpret_cast<uint32_t*>(&hp);
    __nv_bfloat16 la = __float2bfloat16(a - __bfloat162float(ha));
    __nv_bfloat16 lb = __float2bfloat16(b - __bfloat162float(hb));
    __nv_bfloat162 lp; lp.x = la; lp.y = lb;
    lo = *reinterpret_cast<uint32_t*>(&lp);
}

// ---------------------------------------------------------------------------
// W pre-pass: split W[512,256] fp32 -> hi/lo bf16, chunk-major [chunk][n][kk]
// ---------------------------------------------------------------------------
__global__ void convert_w_kernel(const float* __restrict__ W) {
    int n = blockIdx.x;           // 0..255
    int k = threadIdx.x;          // 0..511
    float v = W[(size_t)k * F_OUT + n];
    __nv_bfloat16 hi = __float2bfloat16(v);
    __nv_bfloat16 lo = __float2bfloat16(v - __bfloat162float(hi));
    int idx = (k >> 6) * (F_OUT * KC) + n * KC + (k & (KC - 1));
    g_wt_hi[idx] = hi;
    g_wt_lo[idx] = lo;
}

// ---------------------------------------------------------------------------
// Zero-init output
// ---------------------------------------------------------------------------
__global__ void zero_kernel(float* __restrict__ out, int n4) {
    int i = blockIdx.x * blockDim.x + threadIdx.x;
    float4 z = {0.f, 0.f, 0.f, 0.f};
    if (i < n4) reinterpret_cast<float4*>(out)[i] = z;
}

// ---------------------------------------------------------------------------
// Tensor-core GEMM via mma.sync (3-term bf16 split), fused A conversion,
// 2-stage software pipeline. CTA tile 128x128, 8 warps, warp tile 32x64.
//   - A fp32 prefetched into regs one chunk ahead (LDG hides under MMA),
//     split to hi/lo bf16 and STS'd after the MMA of the previous chunk.
//   - B (pre-split bf16) via cp.async issued one full chunk ahead.
// ---------------------------------------------------------------------------
__global__ void __launch_bounds__(256) gemm_mma_kernel(const float* __restrict__ A, int M) {
    extern __shared__ char smem[];
    const uint32_t sb = smem_to_u32(smem);
    const int tid = threadIdx.x;
    const int wid = tid >> 5;
    const int l   = tid & 31;
    const int warp_m = wid & 3;          // 0..3 -> 32 rows each
    const int warp_n = wid >> 2;         // 0..1 -> 64 cols each

    const int block_m = blockIdx.x * TILE_M;
    const int nblk    = blockIdx.y * 128;

    // ldmatrix per-lane offsets (bytes)
    const uint32_t aoff = (uint32_t)((l & 15) * ROWB + ((l & 16) ? 16 : 0));
    const uint32_t boff = (uint32_t)((((l & 7) + ((l & 16) ? 8 : 0)) * ROWB) + ((l & 8) ? 16 : 0));
    const uint32_t abase = (uint32_t)(warp_m * 32) * ROWB + aoff;
    const uint32_t bbase = (uint32_t)(warp_n * 64) * ROWB + boff;

    // A fill mapping: 2 threads/row, 32 fp32 each
    const int ar = tid >> 1;                       // 0..127
    const int ah = (tid & 1) * 32;                 // 0 or 32
    const bool avalid = (block_m + ar) < M;
    const float* aptr = A + (size_t)(block_m + ar) * F_IN + ah;

    // B fill mapping: 4 iters x (row = idx>>3, seg = idx&7), 16B cp.async
    const __nv_bfloat16* wth = g_wt_hi + (size_t)nblk * KC;
    const __nv_bfloat16* wtl = g_wt_lo + (size_t)nblk * KC;

    float acc[2][8][4];
    #pragma unroll
    for (int i = 0; i < 2; i++)
        #pragma unroll
        for (int j = 0; j < 8; j++)
            #pragma unroll
            for (int q = 0; q < 4; q++)
                acc[i][j][q] = 0.f;

    float4 areg[8];                                // 32 fp32 = this thread's A slice

    // ---- helpers as lambdas ----
    auto lda = [&](int chunk) {
        const float* p = aptr + chunk * KC;
        #pragma unroll
        for (int j = 0; j < 8; ++j) {
            if (avalid) areg[j] = *reinterpret_cast<const float4*>(p + j * 4);
            else        areg[j] = make_float4(0.f, 0.f, 0.f, 0.f);
        }
    };
    auto sts_a = [&](int stage) {
        const uint32_t base = sb + stage * SM_STAGE;
        #pragma unroll
        for (int jj = 0; jj < 4; ++jj) {           // 8 floats per group
            uint32_t h0, h1, h2, h3, l0, l1, l2, l3;
            split_pack2(areg[jj * 2].x, areg[jj * 2].y, h0, l0);
            split_pack2(areg[jj * 2].z, areg[jj * 2].w, h1, l1);
            split_pack2(areg[jj * 2 + 1].x, areg[jj * 2 + 1].y, h2, l2);
            split_pack2(areg[jj * 2 + 1].z, areg[jj * 2 + 1].w, h3, l3);
            const uint32_t off = (uint32_t)(ar * ROWB + (ah + jj * 8) * 2);
            STS128(h0, h1, h2, h3, base + SM_AHI + off);
            STS128(l0, l1, l2, l3, base + SM_ALO + off);
        }
    };
    auto ldb = [&](int chunk, int stage) {
        const uint32_t base = sb + stage * SM_STAGE;
        const size_t cbase = (size_t)chunk * (F_OUT * KC);
        #pragma unroll
        for (int p = 0; p < 4; ++p) {
            const int idx = p * 256 + tid;
            const int row = idx >> 3;
            const int seg = idx & 7;
            const uint32_t soff = (uint32_t)(row * ROWB + seg * 16);
            const size_t goff = cbase + (size_t)row * KC + seg * 8;
            CP_ASYNC16(base + SM_BHI + soff, wth + goff);
            CP_ASYNC16(base + SM_BLO + soff, wtl + goff);
        }
        CP_COMMIT();
    };

    // ---- prologue: fill stage 0, prefetch A for chunk 1 ----
    lda(0);
    ldb(0, 0);
    sts_a(0);
    lda(1);

    for (int c = 0; c < NCHUNK; ++c) {
        const int stage = c & 1;
        CP_WAIT0();                 // B(c) landed (issued a full chunk earlier, except c=0)
        __syncthreads();            // A(c)/B(c) visible everywhere; stage^1 buffers free
        if (c + 1 < NCHUNK) ldb(c + 1, stage ^ 1);

        // ---- MMA over 4 K-steps of 16 on current stage ----
        const uint32_t sbase = sb + stage * SM_STAGE;
        const uint32_t abh = sbase + SM_AHI + abase;
        const uint32_t abl = sbase + SM_ALO + abase;
        const uint32_t bbh = sbase + SM_BHI + bbase;
        const uint32_t bbl = sbase + SM_BLO + bbase;
        #pragma unroll
        for (int ks = 0; ks < 4; ++ks) {
            uint32_t ahf[2][4], alf[2][4];
            #pragma unroll
            for (int i = 0; i < 2; ++i) {
                LDSM_X4(ahf[i], abh + (uint32_t)(i * 16 * ROWB) + ks * 32);
                LDSM_X4(alf[i], abl + (uint32_t)(i * 16 * ROWB) + ks * 32);
            }
            #pragma unroll
            for (int jp = 0; jp < 4; ++jp) {
                uint32_t bhf[4], blf[4];
                LDSM_X4(bhf, bbh + (uint32_t)(jp * 16 * ROWB) + ks * 32);
                LDSM_X4(blf, bbl + (uint32_t)(jp * 16 * ROWB) + ks * 32);
                #pragma unroll
                for (int i = 0; i < 2; ++i) {
                    #pragma unroll
                    for (int jj = 0; jj < 2; ++jj) {
                        const int j = jp * 2 + jj;
                        MMA_BF16(acc[i][j], ahf[i], bhf[jj * 2], bhf[jj * 2 + 1]);
                        MMA_BF16(acc[i][j], ahf[i], blf[jj * 2], blf[jj * 2 + 1]);
                        MMA_BF16(acc[i][j], alf[i], bhf[jj * 2], bhf[jj * 2 + 1]);
                    }
                }
            }
        }

        // ---- stage (c+1): store prefetched A, prefetch A for (c+2) ----
        if (c + 1 < NCHUNK) sts_a(stage ^ 1);
        if (c + 2 < NCHUNK) lda(c + 2);
    }

    // ---- epilogue ----
    const int row0 = block_m + warp_m * 32 + (l >> 2);
    const int col0 = nblk + warp_n * 64 + (l & 3) * 2;
    #pragma unroll
    for (int i = 0; i < 2; ++i) {
        const int row = row0 + i * 16;
        #pragma unroll
        for (int j = 0; j < 8; ++j) {
            const int col = col0 + j * 8;
            if (row < M) {
                float2 v01 = {acc[i][j][0], acc[i][j][1]};
                *reinterpret_cast<float2*>(g_support + (size_t)row * F_OUT + col) = v01;
            }
            if (row + 8 < M) {
                float2 v23 = {acc[i][j][2], acc[i][j][3]};
                *reinterpret_cast<float2*>(g_support + (size_t)(row + 8) * F_OUT + col) = v23;
            }
        }
    }
}

// ---------------------------------------------------------------------------
// SpMM: out[row] += val * support[col], edges row-sorted. (unchanged)
// 64 threads/block, each owning 4 features (float4 gathers). Interior
// segments use plain stores; only first/last segments of a chunk use atomics.
// ---------------------------------------------------------------------------
#define ECHUNK 256
#define SPMM_UNROLL 8

__global__ void __launch_bounds__(64) spmm_kernel(
    const int*   __restrict__ erow,
    const int*   __restrict__ ecol,
    const float* __restrict__ eval,
    float*       __restrict__ out,
    int E)
{
    __shared__ int   srow[ECHUNK];
    __shared__ int   scol[ECHUNK];
    __shared__ float sval[ECHUNK];

    const int f4 = threadIdx.x;                  // feature quad 0..63
    const int e0 = blockIdx.x * ECHUNK;
    const int n  = min(ECHUNK, E - e0);

    for (int i = threadIdx.x; i < n; i += 64) {
        srow[i] = erow[e0 + i];
        scol[i] = ecol[e0 + i];
        sval[i] = eval[e0 + i];
    }
    for (int i = n + threadIdx.x; i < ECHUNK; i += 64) {
        scol[i] = 0;
        sval[i] = 0.f;
    }
    __syncthreads();
    if (n < ECHUNK) {
        int last = srow[n - 1];
        for (int i = n + threadIdx.x; i < ECHUNK; i += 64) srow[i] = last;
        __syncthreads();
    }

    const float4* sup4 = reinterpret_cast<const float4*>(g_support);
    float4* out4 = reinterpret_cast<float4*>(out);

    float4 acc = {0.f, 0.f, 0.f, 0.f};
    int    cur = srow[0];
    bool   first = true;   // current segment may extend into previous chunk

    #pragma unroll 1
    for (int i = 0; i < ECHUNK; i += SPMM_UNROLL) {
        float4 g[SPMM_UNROLL];
        #pragma unroll
        for (int j = 0; j < SPMM_UNROLL; j++) {
            g[j] = __ldg(&sup4[(size_t)scol[i + j] * (F_OUT / 4) + f4]);
        }
        #pragma unroll
        for (int j = 0; j < SPMM_UNROLL; j++) {
            int r = srow[i + j];
            if (r != cur) {
                if (first) {
                    float* p = out + (size_t)cur * F_OUT + f4 * 4;
                    atomicAdd(p + 0, acc.x);
                    atomicAdd(p + 1, acc.y);
                    atomicAdd(p + 2, acc.z);
                    atomicAdd(p + 3, acc.w);
                    first = false;
                } else {
                    out4[(size_t)cur * (F_OUT / 4) + f4] = acc;
                }
                acc.x = acc.y = acc.z = acc.w = 0.f;
                cur = r;
            }
            const float v = sval[i + j];
            acc.x = fmaf(v, g[j].x, acc.x);
            acc.y = fmaf(v, g[j].y, acc.y);
            acc.z = fmaf(v, g[j].z, acc.z);
            acc.w = fmaf(v, g[j].w, acc.w);
        }
    }
    {
        float* p = out + (size_t)cur * F_OUT + f4 * 4;
        atomicAdd(p + 0, acc.x);
        atomicAdd(p + 1, acc.y);
        atomicAdd(p + 2, acc.z);
        atomicAdd(p + 3, acc.w);
    }
}

// ---------------------------------------------------------------------------
extern "C" void kernel_launch(void* const* d_in, const int* in_sizes, int n_in,
                              void* d_out, int out_size) {
    const float* x    = (const float*)d_in[0];   // [N, 512]
    const float* w    = (const float*)d_in[1];   // [512, 256]
    const int*   erow = (const int*)  d_in[2];   // [E]
    const int*   ecol = (const int*)  d_in[3];   // [E]
    const float* eval = (const float*)d_in[4];   // [E]
    float* out = (float*)d_out;                  // [N, 256]

    const int M = in_sizes[0] / F_IN;            // 100000
    const int E = in_sizes[2];                   // 3200000

    // 0) split W into bf16 hi/lo (tiny)
    convert_w_kernel<<<F_OUT, F_IN>>>(w);

    // 1) zero output
    int n4 = out_size / 4;
    zero_kernel<<<(n4 + 255) / 256, 256>>>(out, n4);

    // 2) support = x @ W on tensor cores (fused split + double-buffered)
    cudaFuncSetAttribute(gemm_mma_kernel, cudaFuncAttributeMaxDynamicSharedMemorySize, SM_TOTAL);
    dim3 g1((M + TILE_M - 1) / TILE_M, F_OUT / 128);
    gemm_mma_kernel<<<g1, 256, SM_TOTAL>>>(x, M);

    // 3) scatter-add
    spmm_kernel<<<(E + ECHUNK - 1) / ECHUNK, 64>>>(erow, ecol, eval, out, E);
}

// round 16
// speedup vs baseline: 1.1204x; 1.1204x over previous
#include <cuda_runtime.h>
#include <cuda_bf16.h>
#include <cstdint>

// Problem constants (fixed by the reference)
#define F_IN   512
#define F_OUT  256
#define MAX_NODES 100000
#define KC      32                 // K per chunk (small stages -> occ 2 with 2 buffers)
#define NCHUNK  (F_IN / KC)        // 16
#define TILE_M  128

// ---------------------------------------------------------------------------
// Global scratch (allocation-free per harness rules)
// ---------------------------------------------------------------------------
__device__ float g_support[(size_t)MAX_NODES * F_OUT];                 // 102.4 MB
__device__ __nv_bfloat16 g_wt_hi[NCHUNK * F_OUT * KC];                 // 256 KB, [chunk][n][kk]
__device__ __nv_bfloat16 g_wt_lo[NCHUNK * F_OUT * KC];                 // 256 KB

// ---------------------------------------------------------------------------
// Helpers (baseline PTX only: ldmatrix sm_75+, mma.sync + cp.async sm_80+)
// ---------------------------------------------------------------------------
__device__ __forceinline__ uint32_t smem_to_u32(const void* p) {
    uint32_t a;
    asm("{ .reg .u64 t; cvta.to.shared.u64 t, %1; cvt.u32.u64 %0, t; }" : "=r"(a) : "l"(p));
    return a;
}
#define STS128(r0, r1, r2, r3, addr) \
    asm volatile("st.shared.v4.b32 [%0], {%1, %2, %3, %4};" \
                 :: "r"(addr), "r"(r0), "r"(r1), "r"(r2), "r"(r3) : "memory")
#define CP_ASYNC16(smem, gmem) \
    asm volatile("cp.async.cg.shared.global [%0], [%1], 16;" \
                 :: "r"(smem), "l"(gmem) : "memory")
#define CP_COMMIT()  asm volatile("cp.async.commit_group;" ::: "memory")
#define CP_WAIT0()   asm volatile("cp.async.wait_group 0;" ::: "memory")
#define LDSM_X4(r, addr) \
    asm volatile("ldmatrix.sync.aligned.m8n8.x4.shared.b16 {%0,%1,%2,%3}, [%4];" \
                 : "=r"((r)[0]), "=r"((r)[1]), "=r"((r)[2]), "=r"((r)[3]) : "r"(addr))
#define MMA_BF16(d, a, b0, b1) \
    asm volatile("mma.sync.aligned.m16n8k16.row.col.f32.bf16.bf16.f32 " \
                 "{%0,%1,%2,%3}, {%4,%5,%6,%7}, {%8,%9}, {%0,%1,%2,%3};" \
                 : "+f"((d)[0]), "+f"((d)[1]), "+f"((d)[2]), "+f"((d)[3]) \
                 : "r"((a)[0]), "r"((a)[1]), "r"((a)[2]), "r"((a)[3]), \
                   "r"(b0), "r"(b1))

// Padded SMEM row stride for KC=32: 32 bf16 (64 B) + 16 B pad = 80 B.
// Rows 0-7 land at distinct offsets mod 128 -> conflict-free ldmatrix.
#define ROWB     80
#define SM_AHI   0
#define SM_ALO   (SM_AHI + TILE_M * ROWB)    // 10240
#define SM_BHI   (SM_ALO + TILE_M * ROWB)    // 20480
#define SM_BLO   (SM_BHI + 128 * ROWB)       // 30720
#define SM_STAGE (SM_BLO + 128 * ROWB)       // 40960 B per stage
#define SM_TOTAL (2 * SM_STAGE)              // 81920 B -> 2 CTAs/SM

__device__ __forceinline__ void split_pack2(float a, float b, uint32_t& hi, uint32_t& lo) {
    __nv_bfloat16 ha = __float2bfloat16(a);
    __nv_bfloat16 hb = __float2bfloat16(b);
    __nv_bfloat162 hp; hp.x = ha; hp.y = hb;
    hi = *reinterpret_cast<uint32_t*>(&hp);
    __nv_bfloat16 la = __float2bfloat16(a - __bfloat162float(ha));
    __nv_bfloat16 lb = __float2bfloat16(b - __bfloat162float(hb));
    __nv_bfloat162 lp; lp.x = la; lp.y = lb;
    lo = *reinterpret_cast<uint32_t*>(&lp);
}

// ---------------------------------------------------------------------------
// W pre-pass: split W[512,256] fp32 -> hi/lo bf16, chunk-major [chunk][n][kk]
// ---------------------------------------------------------------------------
__global__ void convert_w_kernel(const float* __restrict__ W) {
    int n = blockIdx.x;           // 0..255
    int k = threadIdx.x;          // 0..511
    float v = W[(size_t)k * F_OUT + n];
    __nv_bfloat16 hi = __float2bfloat16(v);
    __nv_bfloat16 lo = __float2bfloat16(v - __bfloat162float(hi));
    int idx = (k / KC) * (F_OUT * KC) + n * KC + (k & (KC - 1));
    g_wt_hi[idx] = hi;
    g_wt_lo[idx] = lo;
}

// ---------------------------------------------------------------------------
// Zero-init output
// ---------------------------------------------------------------------------
__global__ void zero_kernel(float* __restrict__ out, int n4) {
    int i = blockIdx.x * blockDim.x + threadIdx.x;
    float4 z = {0.f, 0.f, 0.f, 0.f};
    if (i < n4) reinterpret_cast<float4*>(out)[i] = z;
}

// ---------------------------------------------------------------------------
// Tensor-core GEMM via mma.sync (3-term bf16 split), fused A conversion,
// 2-stage pipeline with small (40 KB) stages -> 2 CTAs/SM.
// CTA tile 128x128, 8 warps, warp tile 32x64, K-chunk 32 (16 chunks).
// ---------------------------------------------------------------------------
__global__ void __launch_bounds__(256, 2) gemm_mma_kernel(const float* __restrict__ A, int M) {
    extern __shared__ char smem[];
    const uint32_t sb = smem_to_u32(smem);
    const int tid = threadIdx.x;
    const int wid = tid >> 5;
    const int l   = tid & 31;
    const int warp_m = wid & 3;          // 0..3 -> 32 rows each
    const int warp_n = wid >> 2;         // 0..1 -> 64 cols each

    const int block_m = blockIdx.x * TILE_M;
    const int nblk    = blockIdx.y * 128;

    // ldmatrix per-lane offsets (bytes)
    const uint32_t aoff = (uint32_t)((l & 15) * ROWB + ((l & 16) ? 16 : 0));
    const uint32_t boff = (uint32_t)((((l & 7) + ((l & 16) ? 8 : 0)) * ROWB) + ((l & 8) ? 16 : 0));
    const uint32_t abase = (uint32_t)(warp_m * 32) * ROWB + aoff;
    const uint32_t bbase = (uint32_t)(warp_n * 64) * ROWB + boff;

    // A fill mapping: 2 threads/row, 16 fp32 each
    const int ar = tid >> 1;                       // 0..127
    const int ah = (tid & 1) * 16;                 // 0 or 16
    const bool avalid = (block_m + ar) < M;
    const float* aptr = A + (size_t)(block_m + ar) * F_IN + ah;

    const __nv_bfloat16* wth = g_wt_hi + (size_t)nblk * KC;
    const __nv_bfloat16* wtl = g_wt_lo + (size_t)nblk * KC;

    float acc[2][8][4];
    #pragma unroll
    for (int i = 0; i < 2; i++)
        #pragma unroll
        for (int j = 0; j < 8; j++)
            #pragma unroll
            for (int q = 0; q < 4; q++)
                acc[i][j][q] = 0.f;

    float4 areg[4];                                // 16 fp32 = this thread's A slice

    auto lda = [&](int chunk) {
        const float* p = aptr + chunk * KC;
        #pragma unroll
        for (int j = 0; j < 4; ++j) {
            if (avalid) areg[j] = *reinterpret_cast<const float4*>(p + j * 4);
            else        areg[j] = make_float4(0.f, 0.f, 0.f, 0.f);
        }
    };
    auto sts_a = [&](int stage) {
        const uint32_t base = sb + stage * SM_STAGE;
        #pragma unroll
        for (int jj = 0; jj < 2; ++jj) {           // 8 floats per group
            uint32_t h0, h1, h2, h3, l0, l1, l2, l3;
            split_pack2(areg[jj * 2].x, areg[jj * 2].y, h0, l0);
            split_pack2(areg[jj * 2].z, areg[jj * 2].w, h1, l1);
            split_pack2(areg[jj * 2 + 1].x, areg[jj * 2 + 1].y, h2, l2);
            split_pack2(areg[jj * 2 + 1].z, areg[jj * 2 + 1].w, h3, l3);
            const uint32_t off = (uint32_t)(ar * ROWB + (ah + jj * 8) * 2);
            STS128(h0, h1, h2, h3, base + SM_AHI + off);
            STS128(l0, l1, l2, l3, base + SM_ALO + off);
        }
    };
    auto ldb = [&](int chunk, int stage) {
        const uint32_t base = sb + stage * SM_STAGE;
        const size_t cbase = (size_t)chunk * (F_OUT * KC);
        #pragma unroll
        for (int p = 0; p < 2; ++p) {
            const int idx = p * 256 + tid;         // 512 segs: 128 rows x 4 x 16B
            const int row = idx >> 2;
            const int seg = idx & 3;
            const uint32_t soff = (uint32_t)(row * ROWB + seg * 16);
            const size_t goff = cbase + (size_t)row * KC + seg * 8;
            CP_ASYNC16(base + SM_BHI + soff, wth + goff);
            CP_ASYNC16(base + SM_BLO + soff, wtl + goff);
        }
        CP_COMMIT();
    };

    // ---- prologue: fill stage 0, prefetch A for chunk 1 ----
    lda(0);
    ldb(0, 0);
    sts_a(0);
    lda(1);

    for (int c = 0; c < NCHUNK; ++c) {
        const int stage = c & 1;
        CP_WAIT0();                 // B(c) landed (issued a full chunk earlier, except c=0)
        __syncthreads();            // A(c)/B(c) visible; stage^1 buffers free
        if (c + 1 < NCHUNK) ldb(c + 1, stage ^ 1);

        // ---- MMA over 2 K-steps of 16 on current stage ----
        const uint32_t sbase = sb + stage * SM_STAGE;
        const uint32_t abh = sbase + SM_AHI + abase;
        const uint32_t abl = sbase + SM_ALO + abase;
        const uint32_t bbh = sbase + SM_BHI + bbase;
        const uint32_t bbl = sbase + SM_BLO + bbase;
        #pragma unroll
        for (int ks = 0; ks < 2; ++ks) {
            uint32_t ahf[2][4], alf[2][4];
            #pragma unroll
            for (int i = 0; i < 2; ++i) {
                LDSM_X4(ahf[i], abh + (uint32_t)(i * 16 * ROWB) + ks * 32);
                LDSM_X4(alf[i], abl + (uint32_t)(i * 16 * ROWB) + ks * 32);
            }
            #pragma unroll
            for (int jp = 0; jp < 4; ++jp) {
                uint32_t bhf[4], blf[4];
                LDSM_X4(bhf, bbh + (uint32_t)(jp * 16 * ROWB) + ks * 32);
                LDSM_X4(blf, bbl + (uint32_t)(jp * 16 * ROWB) + ks * 32);
                #pragma unroll
                for (int i = 0; i < 2; ++i) {
                    #pragma unroll
                    for (int jj = 0; jj < 2; ++jj) {
                        const int j = jp * 2 + jj;
                        MMA_BF16(acc[i][j], ahf[i], bhf[jj * 2], bhf[jj * 2 + 1]);
                        MMA_BF16(acc[i][j], ahf[i], blf[jj * 2], blf[jj * 2 + 1]);
                        MMA_BF16(acc[i][j], alf[i], bhf[jj * 2], bhf[jj * 2 + 1]);
                    }
                }
            }
        }

        // ---- stage (c+1): store prefetched A, prefetch A for (c+2) ----
        if (c + 1 < NCHUNK) sts_a(stage ^ 1);
        if (c + 2 < NCHUNK) lda(c + 2);
    }

    // ---- epilogue ----
    const int row0 = block_m + warp_m * 32 + (l >> 2);
    const int col0 = nblk + warp_n * 64 + (l & 3) * 2;
    #pragma unroll
    for (int i = 0; i < 2; ++i) {
        const int row = row0 + i * 16;
        #pragma unroll
        for (int j = 0; j < 8; ++j) {
            const int col = col0 + j * 8;
            if (row < M) {
                float2 v01 = {acc[i][j][0], acc[i][j][1]};
                *reinterpret_cast<float2*>(g_support + (size_t)row * F_OUT + col) = v01;
            }
            if (row + 8 < M) {
                float2 v23 = {acc[i][j][2], acc[i][j][3]};
                *reinterpret_cast<float2*>(g_support + (size_t)(row + 8) * F_OUT + col) = v23;
            }
        }
    }
}

// ---------------------------------------------------------------------------
// SpMM: out[row] += val * support[col], edges row-sorted. (unchanged)
// 64 threads/block, each owning 4 features (float4 gathers). Interior
// segments use plain stores; only first/last segments of a chunk use atomics.
// ---------------------------------------------------------------------------
#define ECHUNK 256
#define SPMM_UNROLL 8

__global__ void __launch_bounds__(64) spmm_kernel(
    const int*   __restrict__ erow,
    const int*   __restrict__ ecol,
    const float* __restrict__ eval,
    float*       __restrict__ out,
    int E)
{
    __shared__ int   srow[ECHUNK];
    __shared__ int   scol[ECHUNK];
    __shared__ float sval[ECHUNK];

    const int f4 = threadIdx.x;                  // feature quad 0..63
    const int e0 = blockIdx.x * ECHUNK;
    const int n  = min(ECHUNK, E - e0);

    for (int i = threadIdx.x; i < n; i += 64) {
        srow[i] = erow[e0 + i];
        scol[i] = ecol[e0 + i];
        sval[i] = eval[e0 + i];
    }
    for (int i = n + threadIdx.x; i < ECHUNK; i += 64) {
        scol[i] = 0;
        sval[i] = 0.f;
    }
    __syncthreads();
    if (n < ECHUNK) {
        int last = srow[n - 1];
        for (int i = n + threadIdx.x; i < ECHUNK; i += 64) srow[i] = last;
        __syncthreads();
    }

    const float4* sup4 = reinterpret_cast<const float4*>(g_support);
    float4* out4 = reinterpret_cast<float4*>(out);

    float4 acc = {0.f, 0.f, 0.f, 0.f};
    int    cur = srow[0];
    bool   first = true;   // current segment may extend into previous chunk

    #pragma unroll 1
    for (int i = 0; i < ECHUNK; i += SPMM_UNROLL) {
        float4 g[SPMM_UNROLL];
        #pragma unroll
        for (int j = 0; j < SPMM_UNROLL; j++) {
            g[j] = __ldg(&sup4[(size_t)scol[i + j] * (F_OUT / 4) + f4]);
        }
        #pragma unroll
        for (int j = 0; j < SPMM_UNROLL; j++) {
            int r = srow[i + j];
            if (r != cur) {
                if (first) {
                    float* p = out + (size_t)cur * F_OUT + f4 * 4;
                    atomicAdd(p + 0, acc.x);
                    atomicAdd(p + 1, acc.y);
                    atomicAdd(p + 2, acc.z);
                    atomicAdd(p + 3, acc.w);
                    first = false;
                } else {
                    out4[(size_t)cur * (F_OUT / 4) + f4] = acc;
                }
                acc.x = acc.y = acc.z = acc.w = 0.f;
                cur = r;
            }
            const float v = sval[i + j];
            acc.x = fmaf(v, g[j].x, acc.x);
            acc.y = fmaf(v, g[j].y, acc.y);
            acc.z = fmaf(v, g[j].z, acc.z);
            acc.w = fmaf(v, g[j].w, acc.w);
        }
    }
    {
        float* p = out + (size_t)cur * F_OUT + f4 * 4;
        atomicAdd(p + 0, acc.x);
        atomicAdd(p + 1, acc.y);
        atomicAdd(p + 2, acc.z);
        atomicAdd(p + 3, acc.w);
    }
}

// ---------------------------------------------------------------------------
extern "C" void kernel_launch(void* const* d_in, const int* in_sizes, int n_in,
                              void* d_out, int out_size) {
    const float* x    = (const float*)d_in[0];   // [N, 512]
    const float* w    = (const float*)d_in[1];   // [512, 256]
    const int*   erow = (const int*)  d_in[2];   // [E]
    const int*   ecol = (const int*)  d_in[3];   // [E]
    const float* eval = (const float*)d_in[4];   // [E]
    float* out = (float*)d_out;                  // [N, 256]

    const int M = in_sizes[0] / F_IN;            // 100000
    const int E = in_sizes[2];                   // 3200000

    // 0) split W into bf16 hi/lo (tiny)
    convert_w_kernel<<<F_OUT, F_IN>>>(w);

    // 1) zero output
    int n4 = out_size / 4;
    zero_kernel<<<(n4 + 255) / 256, 256>>>(out, n4);

    // 2) support = x @ W on tensor cores (fused split, 2-stage, occ 2)
    cudaFuncSetAttribute(gemm_mma_kernel, cudaFuncAttributeMaxDynamicSharedMemorySize, SM_TOTAL);
    dim3 g1((M + TILE_M - 1) / TILE_M, F_OUT / 128);
    gemm_mma_kernel<<<g1, 256, SM_TOTAL>>>(x, M);

    // 3) scatter-add
    spmm_kernel<<<(E + ECHUNK - 1) / ECHUNK, 64>>>(erow, ecol, eval, out, E);
}

// round 17
// speedup vs baseline: 1.1219x; 1.0014x over previous
#include <cuda_runtime.h>
#include <cuda_bf16.h>
#include <cstdint>

// Problem constants (fixed by the reference)
#define F_IN   512
#define F_OUT  256
#define MAX_NODES 100000
#define KC      32                 // K per chunk (small stages -> occ 2 with 2 buffers)
#define NCHUNK  (F_IN / KC)        // 16
#define TILE_M  128

// ---------------------------------------------------------------------------
// Global scratch (allocation-free per harness rules)
// ---------------------------------------------------------------------------
__device__ float g_support[(size_t)MAX_NODES * F_OUT];                 // 102.4 MB
__device__ __nv_bfloat16 g_wt_hi[NCHUNK * F_OUT * KC];                 // 256 KB, [chunk][n][kk]
__device__ __nv_bfloat16 g_wt_lo[NCHUNK * F_OUT * KC];                 // 256 KB

// ---------------------------------------------------------------------------
// Helpers (baseline PTX only: ldmatrix sm_75+, mma.sync + cp.async sm_80+)
// ---------------------------------------------------------------------------
__device__ __forceinline__ uint32_t smem_to_u32(const void* p) {
    uint32_t a;
    asm("{ .reg .u64 t; cvta.to.shared.u64 t, %1; cvt.u32.u64 %0, t; }" : "=r"(a) : "l"(p));
    return a;
}
#define STS128(r0, r1, r2, r3, addr) \
    asm volatile("st.shared.v4.b32 [%0], {%1, %2, %3, %4};" \
                 :: "r"(addr), "r"(r0), "r"(r1), "r"(r2), "r"(r3) : "memory")
#define CP_ASYNC16(smem, gmem) \
    asm volatile("cp.async.cg.shared.global [%0], [%1], 16;" \
                 :: "r"(smem), "l"(gmem) : "memory")
#define CP_COMMIT()  asm volatile("cp.async.commit_group;" ::: "memory")
#define CP_WAIT0()   asm volatile("cp.async.wait_group 0;" ::: "memory")
#define LDSM_X4(r, addr) \
    asm volatile("ldmatrix.sync.aligned.m8n8.x4.shared.b16 {%0,%1,%2,%3}, [%4];" \
                 : "=r"((r)[0]), "=r"((r)[1]), "=r"((r)[2]), "=r"((r)[3]) : "r"(addr))
#define MMA_BF16(d, a, b0, b1) \
    asm volatile("mma.sync.aligned.m16n8k16.row.col.f32.bf16.bf16.f32 " \
                 "{%0,%1,%2,%3}, {%4,%5,%6,%7}, {%8,%9}, {%0,%1,%2,%3};" \
                 : "+f"((d)[0]), "+f"((d)[1]), "+f"((d)[2]), "+f"((d)[3]) \
                 : "r"((a)[0]), "r"((a)[1]), "r"((a)[2]), "r"((a)[3]), \
                   "r"(b0), "r"(b1))

// Padded SMEM row stride for KC=32: 32 bf16 (64 B) + 16 B pad = 80 B.
// Rows 0-7 land at distinct offsets mod 128 -> conflict-free ldmatrix.
#define ROWB     80
#define SM_AHI   0
#define SM_ALO   (SM_AHI + TILE_M * ROWB)    // 10240
#define SM_BHI   (SM_ALO + TILE_M * ROWB)    // 20480
#define SM_BLO   (SM_BHI + 128 * ROWB)       // 30720
#define SM_STAGE (SM_BLO + 128 * ROWB)       // 40960 B per stage
#define SM_TOTAL (2 * SM_STAGE)              // 81920 B -> 2 CTAs/SM

__device__ __forceinline__ void split_pack2(float a, float b, uint32_t& hi, uint32_t& lo) {
    __nv_bfloat16 ha = __float2bfloat16(a);
    __nv_bfloat16 hb = __float2bfloat16(b);
    __nv_bfloat162 hp; hp.x = ha; hp.y = hb;
    hi = *reinterpret_cast<uint32_t*>(&hp);
    __nv_bfloat16 la = __float2bfloat16(a - __bfloat162float(ha));
    __nv_bfloat16 lb = __float2bfloat16(b - __bfloat162float(hb));
    __nv_bfloat162 lp; lp.x = la; lp.y = lb;
    lo = *reinterpret_cast<uint32_t*>(&lp);
}

// ---------------------------------------------------------------------------
// W pre-pass: split W[512,256] fp32 -> hi/lo bf16, chunk-major [chunk][n][kk]
// ---------------------------------------------------------------------------
__global__ void convert_w_kernel(const float* __restrict__ W) {
    int n = blockIdx.x;           // 0..255
    int k = threadIdx.x;          // 0..511
    float v = W[(size_t)k * F_OUT + n];
    __nv_bfloat16 hi = __float2bfloat16(v);
    __nv_bfloat16 lo = __float2bfloat16(v - __bfloat162float(hi));
    int idx = (k / KC) * (F_OUT * KC) + n * KC + (k & (KC - 1));
    g_wt_hi[idx] = hi;
    g_wt_lo[idx] = lo;
}

// ---------------------------------------------------------------------------
// Zero-init output
// ---------------------------------------------------------------------------
__global__ void zero_kernel(float* __restrict__ out, int n4) {
    int i = blockIdx.x * blockDim.x + threadIdx.x;
    float4 z = {0.f, 0.f, 0.f, 0.f};
    if (i < n4) reinterpret_cast<float4*>(out)[i] = z;
}

// ---------------------------------------------------------------------------
// Tensor-core GEMM via mma.sync (3-term bf16 split), fused A conversion,
// 2-stage pipeline, 2 CTAs/SM. CTA tile 128x128, 8 warps, warp tile 32x64.
// GRID: blockIdx.x = n-tile (2), blockIdx.y = m-tile (782) -> the CTA pair
// sharing the same A rows is co-resident, so A's 2nd read hits L2.
// ---------------------------------------------------------------------------
__global__ void __launch_bounds__(256, 2) gemm_mma_kernel(const float* __restrict__ A, int M) {
    extern __shared__ char smem[];
    const uint32_t sb = smem_to_u32(smem);
    const int tid = threadIdx.x;
    const int wid = tid >> 5;
    const int l   = tid & 31;
    const int warp_m = wid & 3;          // 0..3 -> 32 rows each
    const int warp_n = wid >> 2;         // 0..1 -> 64 cols each

    const int block_m = blockIdx.y * TILE_M;
    const int nblk    = blockIdx.x * 128;

    // ldmatrix per-lane offsets (bytes)
    const uint32_t aoff = (uint32_t)((l & 15) * ROWB + ((l & 16) ? 16 : 0));
    const uint32_t boff = (uint32_t)((((l & 7) + ((l & 16) ? 8 : 0)) * ROWB) + ((l & 8) ? 16 : 0));
    const uint32_t abase = (uint32_t)(warp_m * 32) * ROWB + aoff;
    const uint32_t bbase = (uint32_t)(warp_n * 64) * ROWB + boff;

    // A fill mapping: 2 threads/row, 16 fp32 each
    const int ar = tid >> 1;                       // 0..127
    const int ah = (tid & 1) * 16;                 // 0 or 16
    const bool avalid = (block_m + ar) < M;
    const float* aptr = A + (size_t)(block_m + ar) * F_IN + ah;

    const __nv_bfloat16* wth = g_wt_hi + (size_t)nblk * KC;
    const __nv_bfloat16* wtl = g_wt_lo + (size_t)nblk * KC;

    float acc[2][8][4];
    #pragma unroll
    for (int i = 0; i < 2; i++)
        #pragma unroll
        for (int j = 0; j < 8; j++)
            #pragma unroll
            for (int q = 0; q < 4; q++)
                acc[i][j][q] = 0.f;

    float4 areg[4];                                // 16 fp32 = this thread's A slice

    auto lda = [&](int chunk) {
        const float* p = aptr + chunk * KC;
        #pragma unroll
        for (int j = 0; j < 4; ++j) {
            if (avalid) areg[j] = *reinterpret_cast<const float4*>(p + j * 4);
            else        areg[j] = make_float4(0.f, 0.f, 0.f, 0.f);
        }
    };
    auto sts_a = [&](int stage) {
        const uint32_t base = sb + stage * SM_STAGE;
        #pragma unroll
        for (int jj = 0; jj < 2; ++jj) {           // 8 floats per group
            uint32_t h0, h1, h2, h3, l0, l1, l2, l3;
            split_pack2(areg[jj * 2].x, areg[jj * 2].y, h0, l0);
            split_pack2(areg[jj * 2].z, areg[jj * 2].w, h1, l1);
            split_pack2(areg[jj * 2 + 1].x, areg[jj * 2 + 1].y, h2, l2);
            split_pack2(areg[jj * 2 + 1].z, areg[jj * 2 + 1].w, h3, l3);
            const uint32_t off = (uint32_t)(ar * ROWB + (ah + jj * 8) * 2);
            STS128(h0, h1, h2, h3, base + SM_AHI + off);
            STS128(l0, l1, l2, l3, base + SM_ALO + off);
        }
    };
    auto ldb = [&](int chunk, int stage) {
        const uint32_t base = sb + stage * SM_STAGE;
        const size_t cbase = (size_t)chunk * (F_OUT * KC);
        #pragma unroll
        for (int p = 0; p < 2; ++p) {
            const int idx = p * 256 + tid;         // 512 segs: 128 rows x 4 x 16B
            const int row = idx >> 2;
            const int seg = idx & 3;
            const uint32_t soff = (uint32_t)(row * ROWB + seg * 16);
            const size_t goff = cbase + (size_t)row * KC + seg * 8;
            CP_ASYNC16(base + SM_BHI + soff, wth + goff);
            CP_ASYNC16(base + SM_BLO + soff, wtl + goff);
        }
        CP_COMMIT();
    };

    // ---- prologue: fill stage 0, prefetch A for chunk 1 ----
    lda(0);
    ldb(0, 0);
    sts_a(0);
    lda(1);

    for (int c = 0; c < NCHUNK; ++c) {
        const int stage = c & 1;
        CP_WAIT0();                 // B(c) landed (issued a full chunk earlier, except c=0)
        __syncthreads();            // A(c)/B(c) visible; stage^1 buffers free
        if (c + 1 < NCHUNK) ldb(c + 1, stage ^ 1);

        // ---- MMA over 2 K-steps of 16 on current stage ----
        const uint32_t sbase = sb + stage * SM_STAGE;
        const uint32_t abh = sbase + SM_AHI + abase;
        const uint32_t abl = sbase + SM_ALO + abase;
        const uint32_t bbh = sbase + SM_BHI + bbase;
        const uint32_t bbl = sbase + SM_BLO + bbase;
        #pragma unroll
        for (int ks = 0; ks < 2; ++ks) {
            uint32_t ahf[2][4], alf[2][4];
            #pragma unroll
            for (int i = 0; i < 2; ++i) {
                LDSM_X4(ahf[i], abh + (uint32_t)(i * 16 * ROWB) + ks * 32);
                LDSM_X4(alf[i], abl + (uint32_t)(i * 16 * ROWB) + ks * 32);
            }
            #pragma unroll
            for (int jp = 0; jp < 4; ++jp) {
                uint32_t bhf[4], blf[4];
                LDSM_X4(bhf, bbh + (uint32_t)(jp * 16 * ROWB) + ks * 32);
                LDSM_X4(blf, bbl + (uint32_t)(jp * 16 * ROWB) + ks * 32);
                #pragma unroll
                for (int i = 0; i < 2; ++i) {
                    #pragma unroll
                    for (int jj = 0; jj < 2; ++jj) {
                        const int j = jp * 2 + jj;
                        MMA_BF16(acc[i][j], ahf[i], bhf[jj * 2], bhf[jj * 2 + 1]);
                        MMA_BF16(acc[i][j], ahf[i], blf[jj * 2], blf[jj * 2 + 1]);
                        MMA_BF16(acc[i][j], alf[i], bhf[jj * 2], bhf[jj * 2 + 1]);
                    }
                }
            }
        }

        // ---- stage (c+1): store prefetched A, prefetch A for (c+2) ----
        if (c + 1 < NCHUNK) sts_a(stage ^ 1);
        if (c + 2 < NCHUNK) lda(c + 2);
    }

    // ---- epilogue ----
    const int row0 = block_m + warp_m * 32 + (l >> 2);
    const int col0 = nblk + warp_n * 64 + (l & 3) * 2;
    #pragma unroll
    for (int i = 0; i < 2; ++i) {
        const int row = row0 + i * 16;
        #pragma unroll
        for (int j = 0; j < 8; ++j) {
            const int col = col0 + j * 8;
            if (row < M) {
                float2 v01 = {acc[i][j][0], acc[i][j][1]};
                *reinterpret_cast<float2*>(g_support + (size_t)row * F_OUT + col) = v01;
            }
            if (row + 8 < M) {
                float2 v23 = {acc[i][j][2], acc[i][j][3]};
                *reinterpret_cast<float2*>(g_support + (size_t)(row + 8) * F_OUT + col) = v23;
            }
        }
    }
}

// ---------------------------------------------------------------------------
// SpMM: out[row] += val * support[col], edges row-sorted.
// 64 threads/block, each owning 4 features (float4 gathers). Interior
// segments use plain stores; only first/last segments of a chunk use atomics.
// UNROLL 4 (was 8) to cut regs ~51 -> ~35 and raise occupancy ~52% -> ~87%.
// ---------------------------------------------------------------------------
#define ECHUNK 256
#define SPMM_UNROLL 4

__global__ void __launch_bounds__(64) spmm_kernel(
    const int*   __restrict__ erow,
    const int*   __restrict__ ecol,
    const float* __restrict__ eval,
    float*       __restrict__ out,
    int E)
{
    __shared__ int   srow[ECHUNK];
    __shared__ int   scol[ECHUNK];
    __shared__ float sval[ECHUNK];

    const int f4 = threadIdx.x;                  // feature quad 0..63
    const int e0 = blockIdx.x * ECHUNK;
    const int n  = min(ECHUNK, E - e0);

    for (int i = threadIdx.x; i < n; i += 64) {
        srow[i] = erow[e0 + i];
        scol[i] = ecol[e0 + i];
        sval[i] = eval[e0 + i];
    }
    for (int i = n + threadIdx.x; i < ECHUNK; i += 64) {
        scol[i] = 0;
        sval[i] = 0.f;
    }
    __syncthreads();
    if (n < ECHUNK) {
        int last = srow[n - 1];
        for (int i = n + threadIdx.x; i < ECHUNK; i += 64) srow[i] = last;
        __syncthreads();
    }

    const float4* sup4 = reinterpret_cast<const float4*>(g_support);
    float4* out4 = reinterpret_cast<float4*>(out);

    float4 acc = {0.f, 0.f, 0.f, 0.f};
    int    cur = srow[0];
    bool   first = true;   // current segment may extend into previous chunk

    #pragma unroll 1
    for (int i = 0; i < ECHUNK; i += SPMM_UNROLL) {
        float4 g[SPMM_UNROLL];
        #pragma unroll
        for (int j = 0; j < SPMM_UNROLL; j++) {
            g[j] = __ldg(&sup4[(size_t)scol[i + j] * (F_OUT / 4) + f4]);
        }
        #pragma unroll
        for (int j = 0; j < SPMM_UNROLL; j++) {
            int r = srow[i + j];
            if (r != cur) {
                if (first) {
                    float* p = out + (size_t)cur * F_OUT + f4 * 4;
                    atomicAdd(p + 0, acc.x);
                    atomicAdd(p + 1, acc.y);
                    atomicAdd(p + 2, acc.z);
                    atomicAdd(p + 3, acc.w);
                    first = false;
                } else {
                    out4[(size_t)cur * (F_OUT / 4) + f4] = acc;
                }
                acc.x = acc.y = acc.z = acc.w = 0.f;
                cur = r;
            }
            const float v = sval[i + j];
            acc.x = fmaf(v, g[j].x, acc.x);
            acc.y = fmaf(v, g[j].y, acc.y);
            acc.z = fmaf(v, g[j].z, acc.z);
            acc.w = fmaf(v, g[j].w, acc.w);
        }
    }
    {
        float* p = out + (size_t)cur * F_OUT + f4 * 4;
        atomicAdd(p + 0, acc.x);
        atomicAdd(p + 1, acc.y);
        atomicAdd(p + 2, acc.z);
        atomicAdd(p + 3, acc.w);
    }
}

// ---------------------------------------------------------------------------
extern "C" void kernel_launch(void* const* d_in, const int* in_sizes, int n_in,
                              void* d_out, int out_size) {
    const float* x    = (const float*)d_in[0];   // [N, 512]
    const float* w    = (const float*)d_in[1];   // [512, 256]
    const int*   erow = (const int*)  d_in[2];   // [E]
    const int*   ecol = (const int*)  d_in[3];   // [E]
    const float* eval = (const float*)d_in[4];   // [E]
    float* out = (float*)d_out;                  // [N, 256]

    const int M = in_sizes[0] / F_IN;            // 100000
    const int E = in_sizes[2];                   // 3200000

    // 0) split W into bf16 hi/lo (tiny)
    convert_w_kernel<<<F_OUT, F_IN>>>(w);

    // 1) zero output
    int n4 = out_size / 4;
    zero_kernel<<<(n4 + 255) / 256, 256>>>(out, n4);

    // 2) support = x @ W on tensor cores (fused split, 2-stage, occ 2)
    //    n-tile on blockIdx.x so the A-sharing CTA pair is co-resident.
    cudaFuncSetAttribute(gemm_mma_kernel, cudaFuncAttributeMaxDynamicSharedMemorySize, SM_TOTAL);
    dim3 g1(F_OUT / 128, (M + TILE_M - 1) / TILE_M);
    gemm_mma_kernel<<<g1, 256, SM_TOTAL>>>(x, M);

    // 3) scatter-add
    spmm_kernel<<<(E + ECHUNK - 1) / ECHUNK, 64>>>(erow, ecol, eval, out, E);
}